// round 3
// baseline (speedup 1.0000x reference)
#include <cuda_runtime.h>
#include <cuda_fp16.h>
#include <cstdint>
#include <cstddef>

#define DEVINL __device__ __forceinline__

constexpr int MROWS = 16384;
constexpr int KTOT  = 1024;
constexpr int NCOLS = 1024;

// GEMM tiling: CTA 256x128, warp tile 64x64 (8 warps: 4 over M, 2 over N)
constexpr int BM = 256, BN = 128, BK = 64;      // BK in fp16 elements (128B row)
constexpr int STAGES = 4;
constexpr int TPB = 256;
constexpr int NCHUNK = KTOT / BK;               // 16

constexpr int A_BYTES = BM * BK * 2;            // 32 KB
constexpr int B_BYTES = BN * BK * 2;            // 16 KB
constexpr int STAGE_BYTES = A_BYTES + B_BYTES;  // 48 KB
constexpr int SMEM_TOTAL = STAGES * STAGE_BYTES; // 192 KB

// Static device scratch (allocation-free rule)
__device__ __half g_ah[(size_t)MROWS * KTOT];   // A converted to fp16
__device__ __half g_wt[(size_t)NCOLS * KTOT];   // W quantized, [n][k] K-major

// ---------------------------------------------------------------- helpers
DEVINL uint32_t smem_u32(const void* p) {
    uint32_t r;
    asm("{ .reg .u64 t; cvta.to.shared.u64 t, %1; cvt.u32.u64 %0, t; }"
        : "=r"(r) : "l"(p));
    return r;
}
DEVINL uint32_t swz(uint32_t off) {            // SW128: bits[6:4] ^= bits[9:7]
    return off ^ ((off >> 3) & 0x70);
}
DEVINL void cp_async16(uint32_t s, const void* g) {
    asm volatile("cp.async.cg.shared.global [%0], [%1], 16;"
                 :: "r"(s), "l"(g) : "memory");
}
DEVINL void cp_commit() {
    asm volatile("cp.async.commit_group;" ::: "memory");
}
template <int N> DEVINL void cp_wait() {
    asm volatile("cp.async.wait_group %0;" :: "n"(N) : "memory");
}
DEVINL void ldsm_x4(uint32_t* r, uint32_t addr) {
    asm volatile("ldmatrix.sync.aligned.m8n8.x4.shared.b16 {%0,%1,%2,%3}, [%4];"
                 : "=r"(r[0]), "=r"(r[1]), "=r"(r[2]), "=r"(r[3]) : "r"(addr));
}
DEVINL void mma16816(float* c, const uint32_t* a, const uint32_t* b) {
    asm volatile(
        "mma.sync.aligned.m16n8k16.row.col.f32.f16.f16.f32 "
        "{%0,%1,%2,%3}, {%4,%5,%6,%7}, {%8,%9}, {%0,%1,%2,%3};"
        : "+f"(c[0]), "+f"(c[1]), "+f"(c[2]), "+f"(c[3])
        : "r"(a[0]), "r"(a[1]), "r"(a[2]), "r"(a[3]), "r"(b[0]), "r"(b[1]));
}
DEVINL uint32_t pack_half2(float x, float y) {
    __half2 h = __floats2half2_rn(x, y);
    return *reinterpret_cast<uint32_t*>(&h);
}

// ------------------------------------------------ prep: A fp32 -> fp16
__global__ void conv_a_kernel(const float4* __restrict__ a) {
    size_t i = (size_t)blockIdx.x * blockDim.x + threadIdx.x; // one float4 each
    float4 v = a[i];
    uint2 o;
    o.x = pack_half2(v.x, v.y);
    o.y = pack_half2(v.z, v.w);
    reinterpret_cast<uint2*>(g_ah)[i] = o;
}

// ------------------------------------------------ prep: quantize + transpose W
// W[k][n] fp32 -> g_wt[n][k] fp16 in {-0.5, 0, +0.5}
__global__ void quant_transpose_kernel(const float* __restrict__ w) {
    __shared__ __half tile[32][33];
    const int n0 = blockIdx.x * 32;
    const int k0 = blockIdx.y * 32;
    const int tx = threadIdx.x;
    #pragma unroll
    for (int i = threadIdx.y; i < 32; i += 8) {
        float x = w[(size_t)(k0 + i) * NCOLS + n0 + tx];
        x = fminf(fmaxf(x, -0.5f), 0.5f);     // clip [-1+delta, 1-delta]
        float y = rintf(x * 2.0f) * 0.5f;     // round-half-even, step 0.5
        tile[i][tx] = __float2half_rn(y);     // exact in fp16
    }
    __syncthreads();
    #pragma unroll
    for (int i = threadIdx.y; i < 32; i += 8) {
        g_wt[(size_t)(n0 + i) * KTOT + k0 + tx] = tile[tx][i];
    }
}

// ------------------------------------------------------------- main GEMM
__global__ void __launch_bounds__(TPB, 1)
gemm_hmma_kernel(float* __restrict__ C) {
    extern __shared__ char smem[];
    const uint32_t sb = smem_u32(smem);
    const int tid  = threadIdx.x;
    const int lane = tid & 31;
    const int wid  = tid >> 5;
    const int warpM = wid & 3;    // 4 warps over M -> 64 rows each
    const int warpN = wid >> 2;   // 2 warps over N -> 64 cols each

    const int m0 = blockIdx.y * BM;
    const int n0 = blockIdx.x * BN;

    const char* aG = (const char*)(g_ah + (size_t)m0 * KTOT);
    const char* bG = (const char*)(g_wt + (size_t)n0 * KTOT);

    // per-thread cp.async mapping: 32 rows x 8 chunks of 16B per pass
    const int lr = tid >> 3;             // row 0..31
    const int lc = (tid & 7) * 16;       // byte offset within 128B row

    auto load_stage = [&](int kc, int s) {
        const uint32_t aS = sb + s * STAGE_BYTES;
        const uint32_t bS = aS + A_BYTES;
        const char* ag = aG + (size_t)lr * (KTOT * 2) + kc * (BK * 2) + lc;
        const char* bg = bG + (size_t)lr * (KTOT * 2) + kc * (BK * 2) + lc;
        #pragma unroll
        for (int it = 0; it < 8; it++) {            // A: 256 rows
            const uint32_t sw = swz((lr + it * 32) * 128 + lc);
            cp_async16(aS + sw, ag + (size_t)it * 32 * KTOT * 2);
        }
        #pragma unroll
        for (int it = 0; it < 4; it++) {            // B: 128 rows
            const uint32_t sw = swz((lr + it * 32) * 128 + lc);
            cp_async16(bS + sw, bg + (size_t)it * 32 * KTOT * 2);
        }
    };

    // prologue: stages 0..STAGES-2
    #pragma unroll
    for (int s = 0; s < STAGES - 1; s++) {
        load_stage(s, s);
        cp_commit();
    }

    float acc[4][8][4] = {};

    for (int kc = 0; kc < NCHUNK; kc++) {
        cp_wait<STAGES - 2>();
        __syncthreads();   // stage kc ready for all; prev compute finished

        // prefetch stage kc+STAGES-1 into the slot just freed
        if (kc + STAGES - 1 < NCHUNK)
            load_stage(kc + STAGES - 1, (kc + STAGES - 1) % STAGES);
        cp_commit();       // empty groups keep group counts uniform

        const uint32_t aS = sb + (kc % STAGES) * STAGE_BYTES;
        const uint32_t bS = aS + A_BYTES;

        #pragma unroll
        for (int ki = 0; ki < BK / 16; ki++) {           // 4 k16 steps
            uint32_t afr[4][4], bfr[4][4];
            #pragma unroll
            for (int mi = 0; mi < 4; mi++) {
                const int row = warpM * 64 + mi * 16 + (lane & 15);
                const int ko  = ki * 16 + (lane >> 4) * 8;  // k-halves
                ldsm_x4(afr[mi], aS + swz(row * 128 + ko * 2));
            }
            #pragma unroll
            for (int nj = 0; nj < 4; nj++) {             // n16 each
                const int row = warpN * 64 + nj * 16 + ((lane >> 4) << 3) + (lane & 7);
                const int ko  = ki * 16 + ((lane >> 3) & 1) * 8;
                ldsm_x4(bfr[nj], bS + swz(row * 128 + ko * 2));
            }
            #pragma unroll
            for (int mi = 0; mi < 4; mi++)
                #pragma unroll
                for (int nj = 0; nj < 8; nj++)
                    mma16816(acc[mi][nj], afr[mi], &bfr[nj >> 1][(nj & 1) * 2]);
        }
    }

    // ---- epilogue: direct coalesced-by-quad float2 stores
    float* cBase = C + (size_t)(m0 + warpM * 64) * NCOLS + n0 + warpN * 64;
    const int cr = lane >> 2;
    const int cc = (lane & 3) * 2;
    #pragma unroll
    for (int mi = 0; mi < 4; mi++) {
        #pragma unroll
        for (int nj = 0; nj < 8; nj++) {
            float* p0 = cBase + (size_t)(mi * 16 + cr) * NCOLS + nj * 8 + cc;
            float* p1 = p0 + 8 * NCOLS;
            *reinterpret_cast<float2*>(p0) = make_float2(acc[mi][nj][0], acc[mi][nj][1]);
            *reinterpret_cast<float2*>(p1) = make_float2(acc[mi][nj][2], acc[mi][nj][3]);
        }
    }
}

// ---------------------------------------------------------------- launch
extern "C" void kernel_launch(void* const* d_in, const int* in_sizes, int n_in,
                              void* d_out, int out_size) {
    (void)in_sizes; (void)n_in; (void)out_size;
    const float* A = (const float*)d_in[0];   // [16384, 1024] fp32
    const float* W = (const float*)d_in[1];   // [1024, 1024] fp32
    float* C = (float*)d_out;                 // [16384, 1024] fp32

    // A fp32 -> fp16 (one float4 per thread)
    conv_a_kernel<<<(MROWS * KTOT / 4) / 256, 256>>>(
        reinterpret_cast<const float4*>(A));

    // W quantize + transpose
    quant_transpose_kernel<<<dim3(NCOLS / 32, KTOT / 32), dim3(32, 8)>>>(W);

    cudaFuncSetAttribute(gemm_hmma_kernel,
                         cudaFuncAttributeMaxDynamicSharedMemorySize, SMEM_TOTAL);
    gemm_hmma_kernel<<<dim3(NCOLS / BN, MROWS / BM), TPB, SMEM_TOTAL>>>(C);
}

// round 4
// speedup vs baseline: 1.2808x; 1.2808x over previous
#include <cuda_runtime.h>
#include <cuda_fp16.h>
#include <cstdint>
#include <cstddef>

#define DEVINL __device__ __forceinline__

constexpr int MROWS = 16384;
constexpr int KTOT  = 1024;
constexpr int NCOLS = 1024;

// GEMM tiling: CTA 128x128, warp tile 32x64 (8 warps: 4 over M, 2 over N), 2 CTAs/SM
constexpr int BM = 128, BN = 128, BK = 64;      // BK in fp16 elements (128B row)
constexpr int STAGES = 3;
constexpr int TPB = 256;
constexpr int NCHUNK = KTOT / BK;               // 16

constexpr int A_BYTES = BM * BK * 2;            // 16 KB
constexpr int B_BYTES = BN * BK * 2;            // 16 KB
constexpr int STAGE_BYTES = A_BYTES + B_BYTES;  // 32 KB
constexpr int SMEM_TOTAL = STAGES * STAGE_BYTES; // 96 KB (x2 CTAs = 192 KB/SM)

// Static device scratch (allocation-free rule)
__device__ __half g_ah[(size_t)MROWS * KTOT];   // A converted to fp16
__device__ __half g_wt[(size_t)NCOLS * KTOT];   // W quantized, [n][k] K-major

// prep kernel split point
constexpr int CONV_BLOCKS  = 4096;   // 4096 blk * 256 thr * 4 float4 = 4.19M float4
constexpr int QUANT_BLOCKS = (NCOLS / 32) * (KTOT / 32);  // 1024
constexpr int CONV_STRIDE  = CONV_BLOCKS * 256;           // float4 elements

// ---------------------------------------------------------------- helpers
DEVINL uint32_t smem_u32(const void* p) {
    uint32_t r;
    asm("{ .reg .u64 t; cvta.to.shared.u64 t, %1; cvt.u32.u64 %0, t; }"
        : "=r"(r) : "l"(p));
    return r;
}
DEVINL uint32_t swz(uint32_t off) {            // SW128: bits[6:4] ^= bits[9:7]
    return off ^ ((off >> 3) & 0x70);
}
DEVINL void cp_async16(uint32_t s, const void* g) {
    asm volatile("cp.async.cg.shared.global [%0], [%1], 16;"
                 :: "r"(s), "l"(g) : "memory");
}
DEVINL void cp_commit() {
    asm volatile("cp.async.commit_group;" ::: "memory");
}
template <int N> DEVINL void cp_wait() {
    asm volatile("cp.async.wait_group %0;" :: "n"(N) : "memory");
}
DEVINL void ldsm_x4(uint32_t* r, uint32_t addr) {
    asm volatile("ldmatrix.sync.aligned.m8n8.x4.shared.b16 {%0,%1,%2,%3}, [%4];"
                 : "=r"(r[0]), "=r"(r[1]), "=r"(r[2]), "=r"(r[3]) : "r"(addr));
}
DEVINL void mma16816(float* c, const uint32_t* a, const uint32_t* b) {
    asm volatile(
        "mma.sync.aligned.m16n8k16.row.col.f32.f16.f16.f32 "
        "{%0,%1,%2,%3}, {%4,%5,%6,%7}, {%8,%9}, {%0,%1,%2,%3};"
        : "+f"(c[0]), "+f"(c[1]), "+f"(c[2]), "+f"(c[3])
        : "r"(a[0]), "r"(a[1]), "r"(a[2]), "r"(a[3]), "r"(b[0]), "r"(b[1]));
}
DEVINL uint32_t pack_half2(float x, float y) {
    __half2 h = __floats2half2_rn(x, y);
    return *reinterpret_cast<uint32_t*>(&h);
}

// -------------------------------------------- merged prep kernel
// blocks [0, CONV_BLOCKS):            A fp32 -> fp16 (4 float4 per thread, MLP=4)
// blocks [CONV_BLOCKS, +QUANT_BLOCKS): W quantize + transpose
__global__ void prep_kernel(const float4* __restrict__ a,
                            const float* __restrict__ w) {
    const int bid = blockIdx.x;
    const int t   = threadIdx.x;

    if (bid < CONV_BLOCKS) {
        const size_t base = (size_t)bid * 256 + t;
        float4 v0 = a[base];
        float4 v1 = a[base + CONV_STRIDE];
        float4 v2 = a[base + 2 * (size_t)CONV_STRIDE];
        float4 v3 = a[base + 3 * (size_t)CONV_STRIDE];
        uint2 o0 = make_uint2(pack_half2(v0.x, v0.y), pack_half2(v0.z, v0.w));
        uint2 o1 = make_uint2(pack_half2(v1.x, v1.y), pack_half2(v1.z, v1.w));
        uint2 o2 = make_uint2(pack_half2(v2.x, v2.y), pack_half2(v2.z, v2.w));
        uint2 o3 = make_uint2(pack_half2(v3.x, v3.y), pack_half2(v3.z, v3.w));
        uint2* out = reinterpret_cast<uint2*>(g_ah);
        out[base]                          = o0;
        out[base + CONV_STRIDE]            = o1;
        out[base + 2 * (size_t)CONV_STRIDE] = o2;
        out[base + 3 * (size_t)CONV_STRIDE] = o3;
    } else {
        __shared__ __half tile[32][33];
        const int tb = bid - CONV_BLOCKS;
        const int n0 = (tb & 31) * 32;
        const int k0 = (tb >> 5) * 32;
        const int tx = t & 31;
        const int ty = t >> 5;
        #pragma unroll
        for (int i = ty; i < 32; i += 8) {
            float x = w[(size_t)(k0 + i) * NCOLS + n0 + tx];
            x = fminf(fmaxf(x, -0.5f), 0.5f);     // clip [-1+delta, 1-delta]
            float y = rintf(x * 2.0f) * 0.5f;     // round-half-even, step 0.5
            tile[i][tx] = __float2half_rn(y);     // exact in fp16
        }
        __syncthreads();
        #pragma unroll
        for (int i = ty; i < 32; i += 8) {
            g_wt[(size_t)(n0 + i) * KTOT + k0 + tx] = tile[tx][i];
        }
    }
}

// ------------------------------------------------------------- main GEMM
__global__ void __launch_bounds__(TPB, 2)
gemm_hmma_kernel(float* __restrict__ C) {
    extern __shared__ char smem[];
    const uint32_t sb = smem_u32(smem);
    const int tid  = threadIdx.x;
    const int lane = tid & 31;
    const int wid  = tid >> 5;
    const int warpM = wid & 3;    // 4 warps over M -> 32 rows each
    const int warpN = wid >> 2;   // 2 warps over N -> 64 cols each

    const int m0 = blockIdx.y * BM;
    const int n0 = blockIdx.x * BN;

    const char* aG = (const char*)(g_ah + (size_t)m0 * KTOT);
    const char* bG = (const char*)(g_wt + (size_t)n0 * KTOT);

    // per-thread cp.async mapping: 32 rows x 8 chunks of 16B per pass
    const int lr = tid >> 3;             // row 0..31
    const int lc = (tid & 7) * 16;       // byte offset within 128B row
    const uint32_t ld_sw0 = swz(lr * 128 + lc);   // same XOR mask all passes

    auto load_stage = [&](int kc, int s) {
        const uint32_t aS = sb + s * STAGE_BYTES;
        const uint32_t bS = aS + A_BYTES;
        const char* ag = aG + (size_t)lr * (KTOT * 2) + kc * (BK * 2) + lc;
        const char* bg = bG + (size_t)lr * (KTOT * 2) + kc * (BK * 2) + lc;
        #pragma unroll
        for (int it = 0; it < 4; it++) {
            const uint32_t sw = ld_sw0 + it * 32 * 128;
            cp_async16(aS + sw, ag + (size_t)it * 32 * KTOT * 2);
            cp_async16(bS + sw, bg + (size_t)it * 32 * KTOT * 2);
        }
    };

    // hoisted ldmatrix address bases (offset within stage, ki=0)
    uint32_t aBase[2], bBase[4];
    #pragma unroll
    for (int mi = 0; mi < 2; mi++) {
        const int row = warpM * 32 + mi * 16 + (lane & 15);
        const int ko  = (lane >> 4) * 8;
        aBase[mi] = swz(row * 128 + ko * 2);
    }
    #pragma unroll
    for (int nj = 0; nj < 4; nj++) {
        const int row = warpN * 64 + nj * 16 + ((lane >> 4) << 3) + (lane & 7);
        const int ko  = ((lane >> 3) & 1) * 8;
        bBase[nj] = swz(row * 128 + ko * 2) + A_BYTES;
    }

    // prologue: stages 0..STAGES-2
    #pragma unroll
    for (int s = 0; s < STAGES - 1; s++) {
        load_stage(s, s);
        cp_commit();
    }

    float acc[2][8][4] = {};

    for (int kc = 0; kc < NCHUNK; kc++) {
        cp_wait<STAGES - 2>();
        __syncthreads();   // stage kc ready for all; prev compute finished

        // prefetch stage kc+STAGES-1 into the slot just freed
        if (kc + STAGES - 1 < NCHUNK)
            load_stage(kc + STAGES - 1, (kc + STAGES - 1) % STAGES);
        cp_commit();       // empty groups keep group counts uniform

        const uint32_t stS = sb + (kc % STAGES) * STAGE_BYTES;

        #pragma unroll
        for (int ki = 0; ki < BK / 16; ki++) {           // 4 k16 steps
            const uint32_t kOff = ki * 32;               // 16 fp16 = 32 B; XOR-safe
            uint32_t afr[2][4], bfr[4][4];
            #pragma unroll
            for (int mi = 0; mi < 2; mi++)
                ldsm_x4(afr[mi], stS + (aBase[mi] ^ kOff));
            #pragma unroll
            for (int nj = 0; nj < 4; nj++)
                ldsm_x4(bfr[nj], stS + (bBase[nj] ^ kOff));
            #pragma unroll
            for (int mi = 0; mi < 2; mi++)
                #pragma unroll
                for (int nj = 0; nj < 8; nj++)
                    mma16816(acc[mi][nj], afr[mi], &bfr[nj >> 1][(nj & 1) * 2]);
        }
    }

    // ---- epilogue: direct coalesced-by-quad float2 stores
    float* cBase = C + (size_t)(m0 + warpM * 32) * NCOLS + n0 + warpN * 64;
    const int cr = lane >> 2;
    const int cc = (lane & 3) * 2;
    #pragma unroll
    for (int mi = 0; mi < 2; mi++) {
        #pragma unroll
        for (int nj = 0; nj < 8; nj++) {
            float* p0 = cBase + (size_t)(mi * 16 + cr) * NCOLS + nj * 8 + cc;
            float* p1 = p0 + 8 * NCOLS;
            *reinterpret_cast<float2*>(p0) = make_float2(acc[mi][nj][0], acc[mi][nj][1]);
            *reinterpret_cast<float2*>(p1) = make_float2(acc[mi][nj][2], acc[mi][nj][3]);
        }
    }
}

// ---------------------------------------------------------------- launch
extern "C" void kernel_launch(void* const* d_in, const int* in_sizes, int n_in,
                              void* d_out, int out_size) {
    (void)in_sizes; (void)n_in; (void)out_size;
    const float* A = (const float*)d_in[0];   // [16384, 1024] fp32
    const float* W = (const float*)d_in[1];   // [1024, 1024] fp32
    float* C = (float*)d_out;                 // [16384, 1024] fp32

    prep_kernel<<<CONV_BLOCKS + QUANT_BLOCKS, 256>>>(
        reinterpret_cast<const float4*>(A), W);

    cudaFuncSetAttribute(gemm_hmma_kernel,
                         cudaFuncAttributeMaxDynamicSharedMemorySize, SMEM_TOTAL);
    gemm_hmma_kernel<<<dim3(NCOLS / BN, MROWS / BM), TPB, SMEM_TOTAL>>>(C);
}